// round 4
// baseline (speedup 1.0000x reference)
#include <cuda_runtime.h>
#include <cstdint>
#include <cstddef>

#define BATCH 8192
#define IN_F  4096
#define OUT_F 4096

// -------- scratch (static device globals; allocation-free per harness rules) --------
__device__ float  g_xd[(size_t)BATCH * IN_F];   // tf32-rounded dropout+ARD-scaled input
__device__ float  g_w [(size_t)OUT_F * IN_F];   // tf32-rounded sampled weight
__device__ float  g_bias[OUT_F];
__device__ float  g_ard [IN_F];
__device__ double g_kl;

// -------- helpers --------
__device__ __forceinline__ float softplus_f(float x) {
    // stable: max(x,0) + log(1 + exp(-|x|)); MUFU-only fast path
    // (abs err vs log1p ~1e-7, far below the 1e-3 gate)
    return fmaxf(x, 0.0f) + __logf(1.0f + __expf(-fabsf(x)));
}
__device__ __forceinline__ float tf32r(float x) {
    uint32_t r;
    asm("cvt.rna.tf32.f32 %0, %1;" : "=r"(r) : "f"(x));
    return __uint_as_float(r);
}
__device__ __forceinline__ void block_reduce_add_kl(float v) {
    __shared__ float red[32];
    #pragma unroll
    for (int o = 16; o; o >>= 1) v += __shfl_down_sync(0xffffffffu, v, o);
    int lane = threadIdx.x & 31, w = threadIdx.x >> 5;
    if (lane == 0) red[w] = v;
    __syncthreads();
    if (w == 0) {
        v = (lane < (int)(blockDim.x >> 5)) ? red[lane] : 0.0f;
        #pragma unroll
        for (int o = 16; o; o >>= 1) v += __shfl_down_sync(0xffffffffu, v, o);
        if (lane == 0) atomicAdd(&g_kl, (double)v);
    }
}

// -------- kernels --------
__global__ void k_zero() { g_kl = 0.0; }

// bias sample + bias KL + ARD scale + ARD KL (both length 4096)
__global__ void k_small(const float* __restrict__ bmu, const float* __restrict__ brho,
                        const float* __restrict__ aa,  const float* __restrict__ ab,
                        const float* __restrict__ bnoise) {
    int i = blockIdx.x * blockDim.x + threadIdx.x;
    float kl = 0.0f;
    if (i < OUT_F) {
        float bs = softplus_f(brho[i]);
        float mu = bmu[i];
        g_bias[i] = mu + bs * bnoise[i];
        kl += 0.5f * (2.0f * __logf(bs) + 1.0f / (bs * bs) + mu * mu - 1.0f);
        float sa = softplus_f(aa[i]);
        float sb = softplus_f(ab[i]);
        g_ard[i] = sa * sb;
        kl += sa + sb - __logf(sa) - __logf(sb);
    }
    block_reduce_add_kl(kl);
}

// xd = x * dropout_mask * ard_scale, tf32-rounded
__global__ void k_prep_x(const float4* __restrict__ x, const float4* __restrict__ u) {
    int idx = blockIdx.x * blockDim.x + threadIdx.x;   // over BATCH*IN_F/4
    int col4 = idx & (IN_F / 4 - 1);
    float4 xa = x[idx], ua = u[idx];
    float4 arv = ((const float4*)g_ard)[col4];
    const float inv = 1.0f / 0.9f;
    float4 r;
    r.x = tf32r((ua.x < 0.9f ? xa.x * inv : 0.0f) * arv.x);
    r.y = tf32r((ua.y < 0.9f ? xa.y * inv : 0.0f) * arv.y);
    r.z = tf32r((ua.z < 0.9f ? xa.z * inv : 0.0f) * arv.z);
    r.w = tf32r((ua.w < 0.9f ? xa.w * inv : 0.0f) * arv.w);
    ((float4*)g_xd)[idx] = r;
}

// W = mu + softplus(rho)*noise (tf32-rounded) + weight KL accumulation
__global__ void k_prep_w(const float4* __restrict__ mu, const float4* __restrict__ rho,
                         const float4* __restrict__ noise) {
    int idx = blockIdx.x * blockDim.x + threadIdx.x;   // over OUT_F*IN_F/4
    float4 m = mu[idx], r = rho[idx], n = noise[idx];
    float4 w;
    float kl = 0.0f;
    {
        float s = softplus_f(r.x);
        w.x = tf32r(m.x + s * n.x);
        kl += 0.5f * (2.0f * __logf(s) + 1.0f / (s * s) + m.x * m.x - 1.0f);
    }
    {
        float s = softplus_f(r.y);
        w.y = tf32r(m.y + s * n.y);
        kl += 0.5f * (2.0f * __logf(s) + 1.0f / (s * s) + m.y * m.y - 1.0f);
    }
    {
        float s = softplus_f(r.z);
        w.z = tf32r(m.z + s * n.z);
        kl += 0.5f * (2.0f * __logf(s) + 1.0f / (s * s) + m.z * m.z - 1.0f);
    }
    {
        float s = softplus_f(r.w);
        w.w = tf32r(m.w + s * n.w);
        kl += 0.5f * (2.0f * __logf(s) + 1.0f / (s * s) + m.w * m.w - 1.0f);
    }
    ((float4*)g_w)[idx] = w;
    block_reduce_add_kl(kl);
}

__global__ void k_fin(float* __restrict__ out, int pos) {
    out[pos] = (float)g_kl;
}

// -------- GEMM: y[b,o] = sum_k xd[b,k]*w[o,k] + bias[o] --------
#define BM 128
#define BN 128
#define BK 32
#define LDSS 36   // padded row stride (floats): (4r + k) % 32 all distinct -> conflict-free

__device__ __forceinline__ void cp16(float* sdst, const float* gsrc) {
    uint32_t s = (uint32_t)__cvta_generic_to_shared(sdst);
    asm volatile("cp.async.cg.shared.global [%0], [%1], 16;\n" :: "r"(s), "l"(gsrc) : "memory");
}

__global__ void __launch_bounds__(256, 2) k_gemm(float* __restrict__ out) {
    extern __shared__ float smem[];
    float* As = smem;                       // 2 stages * BM * LDSS
    float* Bs = smem + 2 * BM * LDSS;       // 2 stages * BN * LDSS

    const int tid  = threadIdx.x;
    const int lane = tid & 31;
    const int warp = tid >> 5;
    const int warpM = warp >> 2;            // 0..1  -> 64-row slab
    const int warpN = warp & 3;             // 0..3  -> 32-col slab
    const int g  = lane >> 2;               // group id 0..7
    const int tg = lane & 3;                // thread-in-group 0..3

    const float* gA = g_xd + (size_t)blockIdx.y * BM * IN_F;
    const float* gB = g_w  + (size_t)blockIdx.x * BN * IN_F;

    float c[4][4][4];
    #pragma unroll
    for (int a = 0; a < 4; a++)
        #pragma unroll
        for (int b = 0; b < 4; b++)
            #pragma unroll
            for (int d = 0; d < 4; d++) c[a][b][d] = 0.0f;

    auto issue = [&](int s, int k0) {
        #pragma unroll
        for (int i = 0; i < 4; i++) {
            int ch = tid + i * 256;          // 1024 16B chunks for A
            int r = ch >> 3, cc = (ch & 7) << 2;
            cp16(&As[s * BM * LDSS + r * LDSS + cc], gA + (size_t)r * IN_F + k0 + cc);
        }
        #pragma unroll
        for (int i = 0; i < 4; i++) {
            int ch = tid + i * 256;          // 1024 16B chunks for B
            int r = ch >> 3, cc = (ch & 7) << 2;
            cp16(&Bs[s * BN * LDSS + r * LDSS + cc], gB + (size_t)r * IN_F + k0 + cc);
        }
        asm volatile("cp.async.commit_group;\n" ::: "memory");
    };

    auto compute = [&](int s) {
        const float* Ab = As + s * BM * LDSS + (warpM * 64 + g) * LDSS;
        const float* Bb = Bs + s * BN * LDSS + (warpN * 32 + g) * LDSS;
        #pragma unroll
        for (int kk = 0; kk < BK; kk += 8) {
            uint32_t a[4][4], b[4][2];
            #pragma unroll
            for (int mt = 0; mt < 4; mt++) {
                const float* p = Ab + mt * 16 * LDSS + kk + tg;
                a[mt][0] = __float_as_uint(p[0]);
                a[mt][1] = __float_as_uint(p[8 * LDSS]);
                a[mt][2] = __float_as_uint(p[4]);
                a[mt][3] = __float_as_uint(p[8 * LDSS + 4]);
            }
            #pragma unroll
            for (int nt = 0; nt < 4; nt++) {
                const float* p = Bb + nt * 8 * LDSS + kk + tg;
                b[nt][0] = __float_as_uint(p[0]);
                b[nt][1] = __float_as_uint(p[4]);
            }
            #pragma unroll
            for (int mt = 0; mt < 4; mt++)
                #pragma unroll
                for (int nt = 0; nt < 4; nt++)
                    asm volatile(
                        "mma.sync.aligned.m16n8k8.row.col.f32.tf32.tf32.f32 "
                        "{%0,%1,%2,%3}, {%4,%5,%6,%7}, {%8,%9}, {%0,%1,%2,%3};\n"
                        : "+f"(c[mt][nt][0]), "+f"(c[mt][nt][1]),
                          "+f"(c[mt][nt][2]), "+f"(c[mt][nt][3])
                        : "r"(a[mt][0]), "r"(a[mt][1]), "r"(a[mt][2]), "r"(a[mt][3]),
                          "r"(b[nt][0]), "r"(b[nt][1]));
        }
    };

    issue(0, 0);
    const int NT = IN_F / BK;
    for (int kt = 0; kt < NT; ++kt) {
        if (kt + 1 < NT) issue((kt + 1) & 1, (kt + 1) * BK);
        else asm volatile("cp.async.commit_group;\n" ::: "memory");
        asm volatile("cp.async.wait_group 1;\n" ::: "memory");
        __syncthreads();
        compute(kt & 1);
        __syncthreads();
    }

    // epilogue: += bias, write fp32
    const int rowBase = blockIdx.y * BM + warpM * 64 + g;
    const int colBase = blockIdx.x * BN + warpN * 32 + 2 * tg;
    #pragma unroll
    for (int mt = 0; mt < 4; mt++) {
        #pragma unroll
        for (int nt = 0; nt < 4; nt++) {
            int row = rowBase + mt * 16;
            int col = colBase + nt * 8;
            float b0 = g_bias[col], b1 = g_bias[col + 1];
            float2 v0 = make_float2(c[mt][nt][0] + b0, c[mt][nt][1] + b1);
            float2 v1 = make_float2(c[mt][nt][2] + b0, c[mt][nt][3] + b1);
            *(float2*)&out[(size_t)row * OUT_F + col]       = v0;
            *(float2*)&out[(size_t)(row + 8) * OUT_F + col] = v1;
        }
    }
}

// -------- launch --------
extern "C" void kernel_launch(void* const* d_in, const int* in_sizes, int n_in,
                              void* d_out, int out_size) {
    const float* x    = (const float*)d_in[0];
    const float* wmu  = (const float*)d_in[1];
    const float* wrho = (const float*)d_in[2];
    const float* bmu  = (const float*)d_in[3];
    const float* brho = (const float*)d_in[4];
    const float* aa   = (const float*)d_in[5];
    const float* ab   = (const float*)d_in[6];
    const float* wn   = (const float*)d_in[7];
    const float* bn   = (const float*)d_in[8];
    const float* du   = (const float*)d_in[9];
    float* out = (float*)d_out;

    cudaFuncSetAttribute(k_gemm, cudaFuncAttributeMaxDynamicSharedMemorySize, 73728);

    k_zero<<<1, 1>>>();
    k_small<<<OUT_F / 256, 256>>>(bmu, brho, aa, ab, bn);
    k_prep_x<<<(BATCH * IN_F / 4) / 256, 256>>>((const float4*)x, (const float4*)du);
    k_prep_w<<<((size_t)OUT_F * IN_F / 4) / 256, 256>>>(
        (const float4*)wmu, (const float4*)wrho, (const float4*)wn);
    k_gemm<<<dim3(OUT_F / BN, BATCH / BM), 256, 73728>>>(out);
    k_fin<<<1, 1>>>(out, out_size - 1);
}

// round 17
// speedup vs baseline: 1.0769x; 1.0769x over previous
#include <cuda_runtime.h>
#include <cstdint>
#include <cstddef>

#define BATCH 8192
#define IN_F  4096
#define OUT_F 4096

// -------- scratch (static device globals; allocation-free per harness rules) --------
__device__ float  g_xd[(size_t)BATCH * IN_F];   // tf32-rounded dropout+ARD-scaled input
__device__ float  g_w [(size_t)OUT_F * IN_F];   // tf32-rounded sampled weight
__device__ float  g_bias[OUT_F];
__device__ float  g_ard [IN_F];
__device__ double g_kl;

// -------- helpers --------
__device__ __forceinline__ float softplus_f(float x) {
    return fmaxf(x, 0.0f) + __logf(1.0f + __expf(-fabsf(x)));
}
__device__ __forceinline__ float tf32r(float x) {
    uint32_t r;
    asm("cvt.rna.tf32.f32 %0, %1;" : "=r"(r) : "f"(x));
    return __uint_as_float(r);
}
__device__ __forceinline__ void block_reduce_add_kl(float v) {
    __shared__ float red[32];
    #pragma unroll
    for (int o = 16; o; o >>= 1) v += __shfl_down_sync(0xffffffffu, v, o);
    int lane = threadIdx.x & 31, w = threadIdx.x >> 5;
    if (lane == 0) red[w] = v;
    __syncthreads();
    if (w == 0) {
        v = (lane < (int)(blockDim.x >> 5)) ? red[lane] : 0.0f;
        #pragma unroll
        for (int o = 16; o; o >>= 1) v += __shfl_down_sync(0xffffffffu, v, o);
        if (lane == 0) atomicAdd(&g_kl, (double)v);
    }
}

// -------- small/prep kernels (prep_w measured at DRAM roofline; unchanged) --------
__global__ void k_zero() { g_kl = 0.0; }

__global__ void k_small(const float* __restrict__ bmu, const float* __restrict__ brho,
                        const float* __restrict__ aa,  const float* __restrict__ ab,
                        const float* __restrict__ bnoise) {
    int i = blockIdx.x * blockDim.x + threadIdx.x;
    float kl = 0.0f;
    if (i < OUT_F) {
        float bs = softplus_f(brho[i]);
        float mu = bmu[i];
        g_bias[i] = mu + bs * bnoise[i];
        kl += 0.5f * (2.0f * __logf(bs) + 1.0f / (bs * bs) + mu * mu - 1.0f);
        float sa = softplus_f(aa[i]);
        float sb = softplus_f(ab[i]);
        g_ard[i] = sa * sb;
        kl += sa + sb - __logf(sa) - __logf(sb);
    }
    block_reduce_add_kl(kl);
}

__global__ void k_prep_x(const float4* __restrict__ x, const float4* __restrict__ u) {
    int idx = blockIdx.x * blockDim.x + threadIdx.x;
    int col4 = idx & (IN_F / 4 - 1);
    float4 xa = x[idx], ua = u[idx];
    float4 arv = ((const float4*)g_ard)[col4];
    const float inv = 1.0f / 0.9f;
    float4 r;
    r.x = tf32r((ua.x < 0.9f ? xa.x * inv : 0.0f) * arv.x);
    r.y = tf32r((ua.y < 0.9f ? xa.y * inv : 0.0f) * arv.y);
    r.z = tf32r((ua.z < 0.9f ? xa.z * inv : 0.0f) * arv.z);
    r.w = tf32r((ua.w < 0.9f ? xa.w * inv : 0.0f) * arv.w);
    ((float4*)g_xd)[idx] = r;
}

__global__ void k_prep_w(const float4* __restrict__ mu, const float4* __restrict__ rho,
                         const float4* __restrict__ noise) {
    int idx = blockIdx.x * blockDim.x + threadIdx.x;
    float4 m = mu[idx], r = rho[idx], n = noise[idx];
    float4 w;
    float kl = 0.0f;
    {
        float s = softplus_f(r.x);
        w.x = tf32r(m.x + s * n.x);
        kl += 0.5f * (2.0f * __logf(s) + 1.0f / (s * s) + m.x * m.x - 1.0f);
    }
    {
        float s = softplus_f(r.y);
        w.y = tf32r(m.y + s * n.y);
        kl += 0.5f * (2.0f * __logf(s) + 1.0f / (s * s) + m.y * m.y - 1.0f);
    }
    {
        float s = softplus_f(r.z);
        w.z = tf32r(m.z + s * n.z);
        kl += 0.5f * (2.0f * __logf(s) + 1.0f / (s * s) + m.z * m.z - 1.0f);
    }
    {
        float s = softplus_f(r.w);
        w.w = tf32r(m.w + s * n.w);
        kl += 0.5f * (2.0f * __logf(s) + 1.0f / (s * s) + m.w * m.w - 1.0f);
    }
    ((float4*)g_w)[idx] = w;
    block_reduce_add_kl(kl);
}

__global__ void k_fin(float* __restrict__ out, int pos) {
    out[pos] = (float)g_kl;
}

// -------- GEMM: y[b,o] = sum_k xd[b,k]*w[o,k] + bias[o] --------
// mma.sync tf32 path (tcgen05 unavailable: harness PTX target is sm_103, no 'a').
// CTA 128x128x32, 2x2 warps, warp tile 64x64 (mt=4, nt=8):
// 32 LDS per 32 MMAs per K8 (was 24 per 16) -> smem crossbar no longer binds.
#define BM 128
#define BN 128
#define BK 32
#define LDSS 36   // padded row stride (floats): (4r + k) % 32 all distinct -> conflict-free

__device__ __forceinline__ void cp16(float* sdst, const float* gsrc) {
    uint32_t s = (uint32_t)__cvta_generic_to_shared(sdst);
    asm volatile("cp.async.cg.shared.global [%0], [%1], 16;\n" :: "r"(s), "l"(gsrc) : "memory");
}

__global__ void __launch_bounds__(128, 2) k_gemm(float* __restrict__ out) {
    extern __shared__ float smem[];
    float* As = smem;                       // 2 stages * BM * LDSS
    float* Bs = smem + 2 * BM * LDSS;       // 2 stages * BN * LDSS

    const int tid  = threadIdx.x;
    const int lane = tid & 31;
    const int warp = tid >> 5;              // 0..3
    const int warpM = warp >> 1;            // 0..1 -> 64-row slab
    const int warpN = warp & 1;             // 0..1 -> 64-col slab
    const int g  = lane >> 2;               // group id 0..7
    const int tg = lane & 3;                // thread-in-group 0..3

    const float* gA = g_xd + (size_t)blockIdx.y * BM * IN_F;
    const float* gB = g_w  + (size_t)blockIdx.x * BN * IN_F;

    float c[4][8][4];
    #pragma unroll
    for (int a = 0; a < 4; a++)
        #pragma unroll
        for (int b = 0; b < 8; b++)
            #pragma unroll
            for (int d = 0; d < 4; d++) c[a][b][d] = 0.0f;

    auto issue = [&](int s, int k0) {
        #pragma unroll
        for (int i = 0; i < 8; i++) {        // 1024 16B chunks for A
            int ch = tid + i * 128;
            int r = ch >> 3, cc = (ch & 7) << 2;
            cp16(&As[s * BM * LDSS + r * LDSS + cc], gA + (size_t)r * IN_F + k0 + cc);
        }
        #pragma unroll
        for (int i = 0; i < 8; i++) {        // 1024 16B chunks for B
            int ch = tid + i * 128;
            int r = ch >> 3, cc = (ch & 7) << 2;
            cp16(&Bs[s * BN * LDSS + r * LDSS + cc], gB + (size_t)r * IN_F + k0 + cc);
        }
        asm volatile("cp.async.commit_group;\n" ::: "memory");
    };

    auto compute = [&](int s) {
        const float* Ab = As + s * BM * LDSS + (warpM * 64 + g) * LDSS;
        const float* Bb = Bs + s * BN * LDSS + (warpN * 64 + g) * LDSS;
        #pragma unroll
        for (int kk = 0; kk < BK; kk += 8) {
            uint32_t a[4][4], b[8][2];
            #pragma unroll
            for (int mt = 0; mt < 4; mt++) {
                const float* p = Ab + mt * 16 * LDSS + kk + tg;
                a[mt][0] = __float_as_uint(p[0]);
                a[mt][1] = __float_as_uint(p[8 * LDSS]);
                a[mt][2] = __float_as_uint(p[4]);
                a[mt][3] = __float_as_uint(p[8 * LDSS + 4]);
            }
            #pragma unroll
            for (int nt = 0; nt < 8; nt++) {
                const float* p = Bb + nt * 8 * LDSS + kk + tg;
                b[nt][0] = __float_as_uint(p[0]);
                b[nt][1] = __float_as_uint(p[4]);
            }
            #pragma unroll
            for (int mt = 0; mt < 4; mt++)
                #pragma unroll
                for (int nt = 0; nt < 8; nt++)
                    asm volatile(
                        "mma.sync.aligned.m16n8k8.row.col.f32.tf32.tf32.f32 "
                        "{%0,%1,%2,%3}, {%4,%5,%6,%7}, {%8,%9}, {%0,%1,%2,%3};\n"
                        : "+f"(c[mt][nt][0]), "+f"(c[mt][nt][1]),
                          "+f"(c[mt][nt][2]), "+f"(c[mt][nt][3])
                        : "r"(a[mt][0]), "r"(a[mt][1]), "r"(a[mt][2]), "r"(a[mt][3]),
                          "r"(b[nt][0]), "r"(b[nt][1]));
        }
    };

    issue(0, 0);
    const int NT = IN_F / BK;
    for (int kt = 0; kt < NT; ++kt) {
        if (kt + 1 < NT) issue((kt + 1) & 1, (kt + 1) * BK);
        else asm volatile("cp.async.commit_group;\n" ::: "memory");
        asm volatile("cp.async.wait_group 1;\n" ::: "memory");
        __syncthreads();
        compute(kt & 1);
        __syncthreads();
    }

    // epilogue: += bias, write fp32
    const int rowBase = blockIdx.y * BM + warpM * 64 + g;
    const int colBase = blockIdx.x * BN + warpN * 64 + 2 * tg;
    #pragma unroll
    for (int mt = 0; mt < 4; mt++) {
        #pragma unroll
        for (int nt = 0; nt < 8; nt++) {
            int row = rowBase + mt * 16;
            int col = colBase + nt * 8;
            float b0 = g_bias[col], b1 = g_bias[col + 1];
            float2 v0 = make_float2(c[mt][nt][0] + b0, c[mt][nt][1] + b1);
            float2 v1 = make_float2(c[mt][nt][2] + b0, c[mt][nt][3] + b1);
            *(float2*)&out[(size_t)row * OUT_F + col]       = v0;
            *(float2*)&out[(size_t)(row + 8) * OUT_F + col] = v1;
        }
    }
}

// -------- launch --------
extern "C" void kernel_launch(void* const* d_in, const int* in_sizes, int n_in,
                              void* d_out, int out_size) {
    const float* x    = (const float*)d_in[0];
    const float* wmu  = (const float*)d_in[1];
    const float* wrho = (const float*)d_in[2];
    const float* bmu  = (const float*)d_in[3];
    const float* brho = (const float*)d_in[4];
    const float* aa   = (const float*)d_in[5];
    const float* ab   = (const float*)d_in[6];
    const float* wn   = (const float*)d_in[7];
    const float* bn   = (const float*)d_in[8];
    const float* du   = (const float*)d_in[9];
    float* out = (float*)d_out;

    cudaFuncSetAttribute(k_gemm, cudaFuncAttributeMaxDynamicSharedMemorySize, 73728);

    k_zero<<<1, 1>>>();
    k_small<<<OUT_F / 256, 256>>>(bmu, brho, aa, ab, bn);
    k_prep_x<<<(BATCH * IN_F / 4) / 256, 256>>>((const float4*)x, (const float4*)du);
    k_prep_w<<<((size_t)OUT_F * IN_F / 4) / 256, 256>>>(
        (const float4*)wmu, (const float4*)wrho, (const float4*)wn);
    k_gemm<<<dim3(OUT_F / BN, BATCH / BM), 128, 73728>>>(out);
    k_fin<<<1, 1>>>(out, out_size - 1);
}